// round 15
// baseline (speedup 1.0000x reference)
#include <cuda_runtime.h>
#include <cuda_fp16.h>
#include <stdint.h>

#define NBD 512
#define NS  256
#define NE  128
#define SH   136                // halves per A/B tile row (272B)
#define PSTR 72                 // halves per P tile row (144B): 36-word stride, ldsm conflict-free
#define T64  (64*SH*2)          // 17408 B
#define T128 (128*SH*2)         // 34816 B

// smem regions (byte offsets)
#define R_AH 0                  // Xq -> XW hi [128 rows]
#define R_KH (R_AH + T128)      // W image rows 0-63 / keys hi [64 rows]
#define R_KL (R_KH + T64)       // W image rows 64-127 / keys lo; P overlays after GEMM2
#define R_P  R_KL               // P hi [128 rows, PSTR] = 18432 B
#define R_RM (R_KL + 18432)     // 128*2 f32 row-sum partials
#define R_INV (R_RM + 1024)     // 128 f32
#define R_STG (R_INV + 576)     // 32KB raw f32 staging (16B aligned)
#define SMEM_BYTES (R_STG + 32768)   // 105,024 B -> 2 CTAs/SM

typedef uint32_t u32;

// W preconverted fp16 hi image, 128 rows, byte-identical to R_KH..R_KL layout
__device__ __align__(16) char g_Wh[T128];

__device__ __forceinline__ u32 sm2u(const void* p) {
    u32 a;
    asm("{ .reg .u64 t; cvta.to.shared.u64 t, %1; cvt.u32.u64 %0, t; }" : "=r"(a) : "l"(p));
    return a;
}
__device__ __forceinline__ u32 packhf(float a, float b) {
    __half2 h = __floats2half2_rn(a, b);
    return *(u32*)&h;
}
__device__ __forceinline__ float hlo(float x) {
    return x - __half2float(__float2half_rn(x));
}
// Accurate expTanh: exp(1 - 2/(e^{2x}+1))
__device__ __forceinline__ float expTanh(float x) {
    float e2 = __expf(2.0f * x);
    float th = 1.0f - __fdividef(2.0f, e2 + 1.0f);
    return __expf(th);
}
__device__ __forceinline__ void ldsm_x4(u32* r, u32 a) {
    asm volatile("ldmatrix.sync.aligned.m8n8.x4.shared.b16 {%0,%1,%2,%3}, [%4];"
                 : "=r"(r[0]), "=r"(r[1]), "=r"(r[2]), "=r"(r[3]) : "r"(a));
}
__device__ __forceinline__ void ldsm_x4t(u32* r, u32 a) {
    asm volatile("ldmatrix.sync.aligned.m8n8.x4.trans.shared.b16 {%0,%1,%2,%3}, [%4];"
                 : "=r"(r[0]), "=r"(r[1]), "=r"(r[2]), "=r"(r[3]) : "r"(a));
}
__device__ __forceinline__ void mma_hf(float* c, const u32* a, u32 b0, u32 b1) {
    asm volatile(
        "mma.sync.aligned.m16n8k16.row.col.f32.f16.f16.f32 "
        "{%0,%1,%2,%3}, {%4,%5,%6,%7}, {%8,%9}, {%0,%1,%2,%3};"
        : "+f"(c[0]), "+f"(c[1]), "+f"(c[2]), "+f"(c[3])
        : "r"(a[0]), "r"(a[1]), "r"(a[2]), "r"(a[3]), "r"(b0), "r"(b1));
}
__device__ __forceinline__ void cpa16(u32 smem, const void* g) {
    asm volatile("cp.async.cg.shared.global [%0], [%1], 16;" :: "r"(smem), "l"(g));
}
__device__ __forceinline__ void cpa_commit() { asm volatile("cp.async.commit_group;" ::: "memory"); }
template<int N> __device__ __forceinline__ void cpa_wait() {
    asm volatile("cp.async.wait_group %0;" :: "n"(N) : "memory");
}

// Prefetch one raw 64x128 f32 chunk (32KB) into staging. Self-addressed: each
// thread copies exactly the bytes it later converts in conv64_stg.
__device__ __forceinline__ void stage_chunk(u32 sb, const float* __restrict__ src, int tid) {
    const char* s = (const char*)src;
    #pragma unroll
    for (int it = 0; it < 4; ++it) {
        int base = (tid + 256 * it) * 32;
        cpa16(sb + R_STG + (u32)base, s + base);
        cpa16(sb + R_STG + (u32)base + 16, s + base + 16);
    }
    cpa_commit();
}

// Convert staged raw chunk -> fp16 hi+lo key tiles. Reads own-thread staging bytes.
__device__ __forceinline__ void conv64_stg(char* hi, char* lo, const char* stg, int tid) {
    #pragma unroll
    for (int it = 0; it < 4; ++it) {
        int li = tid + 256 * it;          // < 1024
        int r = li >> 4, c8 = li & 15;
        float4 v0 = *(const float4*)(stg + li * 32);
        float4 v1 = *(const float4*)(stg + li * 32 + 16);
        uint4 h = make_uint4(packhf(v0.x, v0.y), packhf(v0.z, v0.w),
                             packhf(v1.x, v1.y), packhf(v1.z, v1.w));
        uint4 l = make_uint4(packhf(hlo(v0.x), hlo(v0.y)), packhf(hlo(v0.z), hlo(v0.w)),
                             packhf(hlo(v1.x), hlo(v1.y)), packhf(hlo(v1.z), hlo(v1.w)));
        int off = r * (SH * 2) + 16 * c8;
        *(uint4*)(hi + off) = h;
        *(uint4*)(lo + off) = l;
    }
}
// [128][128] f32 (global) -> fp16 hi-only tile (Xq)
__device__ __forceinline__ void conv128_h(char* hi, const float* __restrict__ src, int tid) {
    const float4* s4 = (const float4*)src;
    #pragma unroll
    for (int it = 0; it < 8; ++it) {
        int li = tid + 256 * it;          // < 2048
        int r = li >> 4, c8 = li & 15;
        float4 v0 = s4[2 * li], v1 = s4[2 * li + 1];
        uint4 h = make_uint4(packhf(v0.x, v0.y), packhf(v0.z, v0.w),
                             packhf(v1.x, v1.y), packhf(v1.z, v1.w));
        *(uint4*)(hi + r * (SH * 2) + 16 * c8) = h;
    }
}

// ---- prologue: W -> fp16 hi image (128 rows) ----
__global__ void conv_w_kernel(const float* __restrict__ Wg) {
    int li = blockIdx.x * blockDim.x + threadIdx.x;
    if (li >= 4096) return;
    int r = li >> 5, c4 = li & 31;
    const float4* s4 = (const float4*)Wg;
    float4 v = s4[li];
    uint2 h = make_uint2(packhf(v.x, v.y), packhf(v.z, v.w));
    *(uint2*)(g_Wh + r * (SH * 2) + 8 * c4) = h;
}

__global__ void __launch_bounds__(256, 2)
sent_attn_hmma5(const float* __restrict__ Xg, const float* __restrict__ Wg,
                const int* __restrict__ lens, float* __restrict__ out)
{
    extern __shared__ char sm[];
    const u32 sb = sm2u(sm);
    const int tid = threadIdx.x, lane = tid & 31, wid = tid >> 5;
    const int mg = wid >> 1;           // 0..3: 32-row query band
    const int ng = wid & 1;            // 0..1: col group
    const int g = lane >> 2, tig = lane & 3;
    const int qc = blockIdx.x, bd = blockIdx.y;   // qc 0..1 (128-query chunks)
    const float* X = Xg + (size_t)bd * NS * NE;
    const int L = lens[bd];

    const int arow = (lane & 15);
    const int acol8 = (lane >> 4) << 3;

    // hoisted LDSM bases
    const u32 aA0 = sb + R_AH + (u32)(((32 * mg + arow) * SH + acol8) * 2);
    const u32 aW  = sb + R_KH + (u32)((arow * SH + 64 * ng + acol8) * 2);     // G1 B (trans) & G3 B (keys trans)
    const u32 aK2 = sb + R_KH + (u32)(((32 * ng + arow) * SH + acol8) * 2);   // G2 B (non-trans)
    const u32 aP0 = sb + R_P  + (u32)(((32 * mg + arow) * PSTR + acol8) * 2); // G3 A (P)

    const int nch = min(4, (L + 63) >> 6);   // 64-key chunks; keys >= L contribute 0

    // ---- prologue: stage chunk 0, copy W image, convert Xq — all overlapped ----
    stage_chunk(sb, X, tid);                      // group: staging ct=0
    for (int li = tid; li < 2176; li += 256)      // W image 34816B into KH+KL
        cpa16(sb + R_KH + li * 16, g_Wh + li * 16);
    cpa_commit();                                 // group: W
    conv128_h(sm + R_AH, X + qc * 128 * NE, tid);
    cpa_wait<0>();                                // both landed
    __syncthreads();

    // ======= GEMM1: XW = Xq_hi @ W_hi, warp tile 32x64, trans B, k=128 =======
    float c1[2][8][4];
    #pragma unroll
    for (int mt = 0; mt < 2; ++mt)
        #pragma unroll
        for (int nt = 0; nt < 8; ++nt)
            #pragma unroll
            for (int r = 0; r < 4; ++r) c1[mt][nt][r] = 0.f;

    #pragma unroll
    for (int k0 = 0; k0 < 8; ++k0) {
        u32 ah[2][4];
        #pragma unroll
        for (int mt = 0; mt < 2; ++mt)
            ldsm_x4(ah[mt], aA0 + (u32)((16 * mt * SH + k0 * 16) * 2));
        u32 bw[16];
        {
            u32 b0 = aW + (u32)(k0 * 16 * SH * 2);
            ldsm_x4t(bw, b0); ldsm_x4t(bw + 4, b0 + 32);
            ldsm_x4t(bw + 8, b0 + 64); ldsm_x4t(bw + 12, b0 + 96);
        }
        #pragma unroll
        for (int mt = 0; mt < 2; ++mt)
            #pragma unroll
            for (int nt = 0; nt < 8; ++nt)
                mma_hf(c1[mt][nt], ah[mt], bw[2 * nt], bw[2 * nt + 1]);
    }
    __syncthreads();   // RACE FIX: sibling warp still reading A rows

    // ---- epilogue 1: XW hi overwrites region A ----
    #pragma unroll
    for (int mt = 0; mt < 2; ++mt)
        #pragma unroll
        for (int nt = 0; nt < 8; ++nt)
            #pragma unroll
            for (int h = 0; h < 2; ++h) {
                int row = 32 * mg + 16 * mt + g + 8 * h;
                int col = 64 * ng + 8 * nt + 2 * tig;
                *(u32*)(sm + R_AH + (row * SH + col) * 2) = packhf(c1[mt][nt][2 * h], c1[mt][nt][2 * h + 1]);
            }

    // ---- persistent accumulators ----
    float c3[2][8][4];
    #pragma unroll
    for (int mt = 0; mt < 2; ++mt)
        #pragma unroll
        for (int nt = 0; nt < 8; ++nt)
            #pragma unroll
            for (int r = 0; r < 4; ++r) c3[mt][nt][r] = 0.f;
    float sumM[2][2];
    sumM[0][0] = sumM[0][1] = sumM[1][0] = sumM[1][1] = 0.f;

    for (int ct = 0; ct < nch; ++ct) {
        __syncthreads();                     // K/P region free (epi1 or prior G3 done)
        cpa_wait<0>();                       // staging(ct) landed (self-addressed reads)
        conv64_stg(sm + R_KH, sm + R_KL, sm + R_STG, tid);
        __syncthreads();                     // K ready
        if (ct + 1 < nch)
            stage_chunk(sb, X + (ct + 1) * 64 * NE, tid);   // lands during G2/epi2/G3

        // ===== GEMM2: logits[128][64] = XWh @ keys^T (2-term), warp tile 32x32 =====
        float c2[2][4][4];
        #pragma unroll
        for (int mt = 0; mt < 2; ++mt)
            #pragma unroll
            for (int nt = 0; nt < 4; ++nt)
                #pragma unroll
                for (int r = 0; r < 4; ++r) c2[mt][nt][r] = 0.f;

        #pragma unroll
        for (int k0 = 0; k0 < 8; ++k0) {
            u32 ah[2][4];
            #pragma unroll
            for (int mt = 0; mt < 2; ++mt)
                ldsm_x4(ah[mt], aA0 + (u32)((16 * mt * SH + k0 * 16) * 2));
            // hi term
            {
                u32 kb[8];
                u32 b0 = aK2 + (u32)(k0 * 32);
                ldsm_x4(kb, b0);
                ldsm_x4(kb + 4, b0 + (u32)(16 * SH * 2));
                #pragma unroll
                for (int mt = 0; mt < 2; ++mt)
                    #pragma unroll
                    for (int nt = 0; nt < 4; ++nt) {
                        int q = nt >> 1, r2 = nt & 1;
                        mma_hf(c2[mt][nt], ah[mt], kb[4 * q + r2], kb[4 * q + r2 + 2]);
                    }
            }
            // lo term (keys-lo kept: error amplifies through tanh->exp)
            {
                u32 kb[8];
                u32 b0 = aK2 + (u32)(k0 * 32) + (u32)T64;
                ldsm_x4(kb, b0);
                ldsm_x4(kb + 4, b0 + (u32)(16 * SH * 2));
                #pragma unroll
                for (int mt = 0; mt < 2; ++mt)
                    #pragma unroll
                    for (int nt = 0; nt < 4; ++nt) {
                        int q = nt >> 1, r2 = nt & 1;
                        mma_hf(c2[mt][nt], ah[mt], kb[4 * q + r2], kb[4 * q + r2 + 2]);
                    }
            }
        }
        __syncthreads();   // keys-lo reads done before P overlays that region

        // ---- epilogue 2: exp(tanh), mask, row sums, P hi (over keys-lo region) ----
        #pragma unroll
        for (int mt = 0; mt < 2; ++mt)
            #pragma unroll
            for (int nt = 0; nt < 4; ++nt)
                #pragma unroll
                for (int h = 0; h < 2; ++h) {
                    int row = 32 * mg + 16 * mt + g + 8 * h;
                    int col = 32 * ng + 8 * nt + 2 * tig;
                    int t = ct * 64 + col;
                    float p0 = expTanh(c2[mt][nt][2 * h]);
                    float p1 = expTanh(c2[mt][nt][2 * h + 1]);
                    if (t     >= L) p0 = 0.f;
                    if (t + 1 >= L) p1 = 0.f;
                    sumM[mt][h] += p0 + p1;
                    *(u32*)(sm + R_P + (row * PSTR + col) * 2) = packhf(p0, p1);
                }
        __syncthreads();   // P complete (cross-warp k reads in GEMM3)

        // ===== GEMM3: att += Ph @ keys-hi, warp tile 32x64, trans B, k=64 =====
        #pragma unroll
        for (int k0 = 0; k0 < 4; ++k0) {
            u32 ah[2][4];
            #pragma unroll
            for (int mt = 0; mt < 2; ++mt)
                ldsm_x4(ah[mt], aP0 + (u32)((16 * mt * PSTR + k0 * 16) * 2));
            u32 bw[16];
            {
                u32 b0 = aW + (u32)(k0 * 16 * SH * 2);
                ldsm_x4t(bw, b0); ldsm_x4t(bw + 4, b0 + 32);
                ldsm_x4t(bw + 8, b0 + 64); ldsm_x4t(bw + 12, b0 + 96);
            }
            #pragma unroll
            for (int mt = 0; mt < 2; ++mt)
                #pragma unroll
                for (int nt = 0; nt < 8; ++nt)
                    mma_hf(c3[mt][nt], ah[mt], bw[2 * nt], bw[2 * nt + 1]);
        }
    }

    // ---- row-sum reduction (2 ng halves per row) ----
    #pragma unroll
    for (int mt = 0; mt < 2; ++mt)
        #pragma unroll
        for (int h = 0; h < 2; ++h) {
            float v = sumM[mt][h];
            v += __shfl_xor_sync(0xffffffffu, v, 1);
            v += __shfl_xor_sync(0xffffffffu, v, 2);
            if (tig == 0) {
                int row = 32 * mg + 16 * mt + g + 8 * h;
                ((float*)(sm + R_RM))[row * 2 + ng] = v;
            }
        }
    __syncthreads();
    if (tid < 128) {
        const float* rm = (const float*)(sm + R_RM);
        ((float*)(sm + R_INV))[tid] = 1.0f / (rm[tid * 2] + rm[tid * 2 + 1]);
    }
    __syncthreads();

    // ---- output: renormalize, STG.64 ----
    float* obase = out + ((size_t)bd * NS + qc * 128) * NE;
    const float* invp = (const float*)(sm + R_INV);
    #pragma unroll
    for (int mt = 0; mt < 2; ++mt)
        #pragma unroll
        for (int h = 0; h < 2; ++h) {
            int row = 32 * mg + 16 * mt + g + 8 * h;
            float iv = invp[row];
            #pragma unroll
            for (int nt = 0; nt < 8; ++nt) {
                int col = 64 * ng + 8 * nt + 2 * tig;
                float2 v = make_float2(c3[mt][nt][2 * h] * iv, c3[mt][nt][2 * h + 1] * iv);
                *(float2*)(obase + row * NE + col) = v;
            }
        }
}

extern "C" void kernel_launch(void* const* d_in, const int* in_sizes, int n_in,
                              void* d_out, int out_size)
{
    const float* X    = (const float*)d_in[0];   // words_enc (8,64,256,128) f32
    const float* W    = (const float*)d_in[1];   // W (128,128) f32
    const int*   lens = (const int*)d_in[2];     // valid_words_len (8,64) i32
    float*       out  = (float*)d_out;           // (8,64,256,128) f32

    conv_w_kernel<<<16, 256>>>(W);               // preconvert W fp16 hi image

    cudaFuncSetAttribute(sent_attn_hmma5, cudaFuncAttributeMaxDynamicSharedMemorySize, SMEM_BYTES);
    dim3 grid(2, NBD, 1);   // 2 query chunks x 512 sentences
    dim3 block(256, 1, 1);
    sent_attn_hmma5<<<grid, block, SMEM_BYTES>>>(X, W, lens, out);
}

// round 16
// speedup vs baseline: 1.0660x; 1.0660x over previous
#include <cuda_runtime.h>
#include <cuda_fp16.h>
#include <stdint.h>

#define NBD 512
#define NS  256
#define NE  128
#define SH   136                // halves per A/B tile row (272B)
#define PSTR 72                 // halves per P tile row (144B)
#define T64  (64*SH*2)          // 17408 B
#define T128 (128*SH*2)         // 34816 B

// smem regions (byte offsets) — R14 layout
#define R_AH 0                  // Xq -> XW hi [128 rows]
#define R_KH (R_AH + T128)      // W image rows 0-63 / keys hi
#define R_KL (R_KH + T64)       // W image rows 64-127 / keys lo
#define R_PH (R_KL + T64)       // P hi [128 rows, PSTR]
#define R_RM (R_PH + 128*PSTR*2)
#define R_INV (R_RM + 1024)
#define SMEM_BYTES (R_INV + 512 + 256)   // ~89.9KB -> 2 CTAs/SM

typedef uint32_t u32;

__device__ __align__(16) char g_Wh[T128];

// pairwise barrier: the 2 warps (ng=0,1) of one mg band; ids 1..4
#define BAR_PAIR(mgv) asm volatile("bar.sync %0, 64;" :: "r"(1 + (mgv)) : "memory")

__device__ __forceinline__ u32 sm2u(const void* p) {
    u32 a;
    asm("{ .reg .u64 t; cvta.to.shared.u64 t, %1; cvt.u32.u64 %0, t; }" : "=r"(a) : "l"(p));
    return a;
}
__device__ __forceinline__ u32 packhf(float a, float b) {
    __half2 h = __floats2half2_rn(a, b);
    return *(u32*)&h;
}
__device__ __forceinline__ float hlo(float x) {
    return x - __half2float(__float2half_rn(x));
}
__device__ __forceinline__ float expTanh(float x) {
    float e2 = __expf(2.0f * x);
    float th = 1.0f - __fdividef(2.0f, e2 + 1.0f);
    return __expf(th);
}
__device__ __forceinline__ void ldsm_x4(u32* r, u32 a) {
    asm volatile("ldmatrix.sync.aligned.m8n8.x4.shared.b16 {%0,%1,%2,%3}, [%4];"
                 : "=r"(r[0]), "=r"(r[1]), "=r"(r[2]), "=r"(r[3]) : "r"(a));
}
__device__ __forceinline__ void ldsm_x4t(u32* r, u32 a) {
    asm volatile("ldmatrix.sync.aligned.m8n8.x4.trans.shared.b16 {%0,%1,%2,%3}, [%4];"
                 : "=r"(r[0]), "=r"(r[1]), "=r"(r[2]), "=r"(r[3]) : "r"(a));
}
__device__ __forceinline__ void mma_hf(float* c, const u32* a, u32 b0, u32 b1) {
    asm volatile(
        "mma.sync.aligned.m16n8k16.row.col.f32.f16.f16.f32 "
        "{%0,%1,%2,%3}, {%4,%5,%6,%7}, {%8,%9}, {%0,%1,%2,%3};"
        : "+f"(c[0]), "+f"(c[1]), "+f"(c[2]), "+f"(c[3])
        : "r"(a[0]), "r"(a[1]), "r"(a[2]), "r"(a[3]), "r"(b0), "r"(b1));
}
__device__ __forceinline__ void cpa16(u32 smem, const void* g) {
    asm volatile("cp.async.cg.shared.global [%0], [%1], 16;" :: "r"(smem), "l"(g));
}
__device__ __forceinline__ void cpa_commit() { asm volatile("cp.async.commit_group;" ::: "memory"); }
template<int N> __device__ __forceinline__ void cpa_wait() {
    asm volatile("cp.async.wait_group %0;" :: "n"(N) : "memory");
}

// convert one 8-float segment into hi/lo tiles at (row r, col8 c8)
__device__ __forceinline__ void conv_seg(char* hi, char* lo, float4 v0, float4 v1, int r, int c8) {
    uint4 h = make_uint4(packhf(v0.x, v0.y), packhf(v0.z, v0.w),
                         packhf(v1.x, v1.y), packhf(v1.z, v1.w));
    uint4 l = make_uint4(packhf(hlo(v0.x), hlo(v0.y)), packhf(hlo(v0.z), hlo(v0.w)),
                         packhf(hlo(v1.x), hlo(v1.y)), packhf(hlo(v1.z), hlo(v1.w)));
    int off = r * (SH * 2) + 16 * c8;
    *(uint4*)(hi + off) = h;
    *(uint4*)(lo + off) = l;
}

// [64][128] keys -> hi+lo; it=0 segment comes from prefetch registers
__device__ __forceinline__ void conv64_hl_pf(char* hi, char* lo, const float* __restrict__ src,
                                             int tid, float4 pf0, float4 pf1) {
    conv_seg(hi, lo, pf0, pf1, tid >> 4, tid & 15);
    const float4* s4 = (const float4*)src;
    #pragma unroll
    for (int it = 1; it < 4; ++it) {
        int li = tid + 256 * it;
        conv_seg(hi, lo, s4[2 * li], s4[2 * li + 1], li >> 4, li & 15);
    }
}
// [128][128] Xq -> hi-only
__device__ __forceinline__ void conv128_h(char* hi, const float* __restrict__ src, int tid) {
    const float4* s4 = (const float4*)src;
    #pragma unroll
    for (int it = 0; it < 8; ++it) {
        int li = tid + 256 * it;
        int r = li >> 4, c8 = li & 15;
        float4 v0 = s4[2 * li], v1 = s4[2 * li + 1];
        uint4 h = make_uint4(packhf(v0.x, v0.y), packhf(v0.z, v0.w),
                             packhf(v1.x, v1.y), packhf(v1.z, v1.w));
        *(uint4*)(hi + r * (SH * 2) + 16 * c8) = h;
    }
}

__global__ void conv_w_kernel(const float* __restrict__ Wg) {
    int li = blockIdx.x * blockDim.x + threadIdx.x;
    if (li >= 4096) return;
    int r = li >> 5, c4 = li & 31;
    const float4* s4 = (const float4*)Wg;
    float4 v = s4[li];
    uint2 h = make_uint2(packhf(v.x, v.y), packhf(v.z, v.w));
    *(uint2*)(g_Wh + r * (SH * 2) + 8 * c4) = h;
}

__global__ void __launch_bounds__(256, 2)
sent_attn_hmma6(const float* __restrict__ Xg, const float* __restrict__ Wg,
                const int* __restrict__ lens, float* __restrict__ out)
{
    extern __shared__ char sm[];
    const u32 sb = sm2u(sm);
    const int tid = threadIdx.x, lane = tid & 31, wid = tid >> 5;
    const int mg = wid >> 1;           // 0..3: 32-row query band
    const int ng = wid & 1;            // 0..1
    const int g = lane >> 2, tig = lane & 3;
    const int qc = blockIdx.x, bd = blockIdx.y;
    const float* X = Xg + (size_t)bd * NS * NE;
    const int L = lens[bd];

    const int arow = (lane & 15);
    const int acol8 = (lane >> 4) << 3;

    const u32 aA0 = sb + R_AH + (u32)(((32 * mg + arow) * SH + acol8) * 2);
    const u32 aW  = sb + R_KH + (u32)((arow * SH + 64 * ng + acol8) * 2);
    const u32 aK2 = sb + R_KH + (u32)(((32 * ng + arow) * SH + acol8) * 2);
    const u32 aP0 = sb + R_PH + (u32)(((32 * mg + arow) * PSTR + acol8) * 2);

    const int nch = min(4, (L + 63) >> 6);

    // ---- prologue: W image via cp.async, Xq conversion, chunk-0 prefetch ----
    for (int li = tid; li < 2176; li += 256)
        cpa16(sb + R_KH + li * 16, g_Wh + li * 16);
    cpa_commit();
    float4 pf0, pf1;                 // prefetch: rows 0-15 segment of next key chunk
    {
        const float4* s4 = (const float4*)X;
        pf0 = s4[2 * tid]; pf1 = s4[2 * tid + 1];
    }
    conv128_h(sm + R_AH, X + qc * 128 * NE, tid);
    cpa_wait<0>();
    __syncthreads();

    // ======= GEMM1: XW = Xq_hi @ W_hi, warp tile 32x64, trans B, k=128 =======
    float c1[2][8][4];
    #pragma unroll
    for (int mt = 0; mt < 2; ++mt)
        #pragma unroll
        for (int nt = 0; nt < 8; ++nt)
            #pragma unroll
            for (int r = 0; r < 4; ++r) c1[mt][nt][r] = 0.f;

    #pragma unroll
    for (int k0 = 0; k0 < 8; ++k0) {
        u32 ah[2][4];
        #pragma unroll
        for (int mt = 0; mt < 2; ++mt)
            ldsm_x4(ah[mt], aA0 + (u32)((16 * mt * SH + k0 * 16) * 2));
        u32 bw[16];
        {
            u32 b0 = aW + (u32)(k0 * 16 * SH * 2);
            ldsm_x4t(bw, b0); ldsm_x4t(bw + 4, b0 + 32);
            ldsm_x4t(bw + 8, b0 + 64); ldsm_x4t(bw + 12, b0 + 96);
        }
        #pragma unroll
        for (int mt = 0; mt < 2; ++mt)
            #pragma unroll
            for (int nt = 0; nt < 8; ++nt)
                mma_hf(c1[mt][nt], ah[mt], bw[2 * nt], bw[2 * nt + 1]);
    }
    BAR_PAIR(mg);   // RACE FIX, pairwise: only the ng-pair of this band reads/writes these A rows

    // ---- epilogue 1: XW hi overwrites region A (own band) ----
    #pragma unroll
    for (int mt = 0; mt < 2; ++mt)
        #pragma unroll
        for (int nt = 0; nt < 8; ++nt)
            #pragma unroll
            for (int h = 0; h < 2; ++h) {
                int row = 32 * mg + 16 * mt + g + 8 * h;
                int col = 64 * ng + 8 * nt + 2 * tig;
                *(u32*)(sm + R_AH + (row * SH + col) * 2) = packhf(c1[mt][nt][2 * h], c1[mt][nt][2 * h + 1]);
            }

    // ---- persistent accumulators ----
    float c3[2][8][4];
    #pragma unroll
    for (int mt = 0; mt < 2; ++mt)
        #pragma unroll
        for (int nt = 0; nt < 8; ++nt)
            #pragma unroll
            for (int r = 0; r < 4; ++r) c3[mt][nt][r] = 0.f;
    float sumM[2][2];
    sumM[0][0] = sumM[0][1] = sumM[1][0] = sumM[1][1] = 0.f;

    for (int ct = 0; ct < nch; ++ct) {
        __syncthreads();                     // K free (epi1 visible / prior G2+G3 key reads done)
        conv64_hl_pf(sm + R_KH, sm + R_KL, X + ct * 64 * NE, tid, pf0, pf1);
        __syncthreads();                     // K ready

        // ===== GEMM2: logits[128][64] = XWh @ keys^T (2-term), warp tile 32x32 =====
        float c2[2][4][4];
        #pragma unroll
        for (int mt = 0; mt < 2; ++mt)
            #pragma unroll
            for (int nt = 0; nt < 4; ++nt)
                #pragma unroll
                for (int r = 0; r < 4; ++r) c2[mt][nt][r] = 0.f;

        #pragma unroll
        for (int k0 = 0; k0 < 8; ++k0) {
            u32 ah[2][4];
            #pragma unroll
            for (int mt = 0; mt < 2; ++mt)
                ldsm_x4(ah[mt], aA0 + (u32)((16 * mt * SH + k0 * 16) * 2));
            {   // hi term
                u32 kb[8];
                u32 b0 = aK2 + (u32)(k0 * 32);
                ldsm_x4(kb, b0);
                ldsm_x4(kb + 4, b0 + (u32)(16 * SH * 2));
                #pragma unroll
                for (int mt = 0; mt < 2; ++mt)
                    #pragma unroll
                    for (int nt = 0; nt < 4; ++nt) {
                        int q = nt >> 1, r2 = nt & 1;
                        mma_hf(c2[mt][nt], ah[mt], kb[4 * q + r2], kb[4 * q + r2 + 2]);
                    }
            }
            {   // lo term (kept: error amplifies through tanh->exp)
                u32 kb[8];
                u32 b0 = aK2 + (u32)(k0 * 32) + (u32)T64;
                ldsm_x4(kb, b0);
                ldsm_x4(kb + 4, b0 + (u32)(16 * SH * 2));
                #pragma unroll
                for (int mt = 0; mt < 2; ++mt)
                    #pragma unroll
                    for (int nt = 0; nt < 4; ++nt) {
                        int q = nt >> 1, r2 = nt & 1;
                        mma_hf(c2[mt][nt], ah[mt], kb[4 * q + r2], kb[4 * q + r2 + 2]);
                    }
            }
        }

        // ---- prefetch next chunk's first rows (hidden behind epi2 + G3) ----
        if (ct + 1 < nch) {
            const float4* s4 = (const float4*)(X + (ct + 1) * 64 * NE);
            pf0 = s4[2 * tid]; pf1 = s4[2 * tid + 1];
        }

        // ---- epilogue 2: exp(tanh), mask, row sums, P hi (own band) ----
        #pragma unroll
        for (int mt = 0; mt < 2; ++mt)
            #pragma unroll
            for (int nt = 0; nt < 4; ++nt)
                #pragma unroll
                for (int h = 0; h < 2; ++h) {
                    int row = 32 * mg + 16 * mt + g + 8 * h;
                    int col = 32 * ng + 8 * nt + 2 * tig;
                    int t = ct * 64 + col;
                    float p0 = expTanh(c2[mt][nt][2 * h]);
                    float p1 = expTanh(c2[mt][nt][2 * h + 1]);
                    if (t     >= L) p0 = 0.f;
                    if (t + 1 >= L) p1 = 0.f;
                    sumM[mt][h] += p0 + p1;
                    *(u32*)(sm + R_PH + (row * PSTR + col) * 2) = packhf(p0, p1);
                }
        BAR_PAIR(mg);   // pairwise: G3 reads P rows of own band only -> mg pairs slide
                        // (one pair's MUFU epilogue overlaps another pair's G3 tensor work)

        // ===== GEMM3: att += Ph @ keys-hi, warp tile 32x64, trans B, k=64 =====
        #pragma unroll
        for (int k0 = 0; k0 < 4; ++k0) {
            u32 ah[2][4];
            #pragma unroll
            for (int mt = 0; mt < 2; ++mt)
                ldsm_x4(ah[mt], aP0 + (u32)((16 * mt * PSTR + k0 * 16) * 2));
            u32 bw[16];
            {
                u32 b0 = aW + (u32)(k0 * 16 * SH * 2);
                ldsm_x4t(bw, b0); ldsm_x4t(bw + 4, b0 + 32);
                ldsm_x4t(bw + 8, b0 + 64); ldsm_x4t(bw + 12, b0 + 96);
            }
            #pragma unroll
            for (int mt = 0; mt < 2; ++mt)
                #pragma unroll
                for (int nt = 0; nt < 8; ++nt)
                    mma_hf(c3[mt][nt], ah[mt], bw[2 * nt], bw[2 * nt + 1]);
        }
    }

    // ---- row-sum reduction ----
    #pragma unroll
    for (int mt = 0; mt < 2; ++mt)
        #pragma unroll
        for (int h = 0; h < 2; ++h) {
            float v = sumM[mt][h];
            v += __shfl_xor_sync(0xffffffffu, v, 1);
            v += __shfl_xor_sync(0xffffffffu, v, 2);
            if (tig == 0) {
                int row = 32 * mg + 16 * mt + g + 8 * h;
                ((float*)(sm + R_RM))[row * 2 + ng] = v;
            }
        }
    __syncthreads();
    if (tid < 128) {
        const float* rm = (const float*)(sm + R_RM);
        ((float*)(sm + R_INV))[tid] = 1.0f / (rm[tid * 2] + rm[tid * 2 + 1]);
    }
    __syncthreads();

    // ---- output: renormalize, STG.64 ----
    float* obase = out + ((size_t)bd * NS + qc * 128) * NE;
    const float* invp = (const float*)(sm + R_INV);
    #pragma unroll
    for (int mt = 0; mt < 2; ++mt)
        #pragma unroll
        for (int h = 0; h < 2; ++h) {
            int row = 32 * mg + 16 * mt + g + 8 * h;
            float iv = invp[row];
            #pragma unroll
            for (int nt = 0; nt < 8; ++nt) {
                int col = 64 * ng + 8 * nt + 2 * tig;
                float2 v = make_float2(c3[mt][nt][2 * h] * iv, c3[mt][nt][2 * h + 1] * iv);
                *(float2*)(obase + row * NE + col) = v;
            }
        }
}

extern "C" void kernel_launch(void* const* d_in, const int* in_sizes, int n_in,
                              void* d_out, int out_size)
{
    const float* X    = (const float*)d_in[0];   // words_enc (8,64,256,128) f32
    const float* W    = (const float*)d_in[1];   // W (128,128) f32
    const int*   lens = (const int*)d_in[2];     // valid_words_len (8,64) i32
    float*       out  = (float*)d_out;           // (8,64,256,128) f32

    conv_w_kernel<<<16, 256>>>(W);               // preconvert W fp16 hi image

    cudaFuncSetAttribute(sent_attn_hmma6, cudaFuncAttributeMaxDynamicSharedMemorySize, SMEM_BYTES);
    dim3 grid(2, NBD, 1);   // 2 query chunks x 512 sentences
    dim3 block(256, 1, 1);
    sent_attn_hmma6<<<grid, block, SMEM_BYTES>>>(X, W, lens, out);
}

// round 17
// speedup vs baseline: 1.1254x; 1.0558x over previous
#include <cuda_runtime.h>
#include <cuda_fp16.h>
#include <stdint.h>

#define NBD 512
#define NS  256
#define NE  128
#define SH   136                // halves per A/B tile row (272B)
#define PSTR 72                 // halves per P tile row (144B)
#define T64  (64*SH*2)          // 17408 B
#define T128 (128*SH*2)         // 34816 B

// smem regions (byte offsets)
#define R_AH 0                  // Xq -> XW hi [128 rows]
#define R_KH (R_AH + T128)      // W pass hi / keys hi [64 rows]
#define R_KL (R_KH + T64)       // W pass lo (chunk loop: unused)
#define R_PH (R_KL + T64)       // P hi [128 rows, PSTR]
#define R_RM (R_PH + 128*PSTR*2)
#define R_INV (R_RM + 1024)
#define SMEM_BYTES (R_INV + 512 + 256)   // ~89.9KB -> 2 CTAs/SM

typedef uint32_t u32;

// W preconverted fp16: [pass][hi 17408B | lo 17408B], byte-identical to KH..KL
__device__ __align__(16) char g_Wbf[2][2 * T64];

__device__ __forceinline__ u32 sm2u(const void* p) {
    u32 a;
    asm("{ .reg .u64 t; cvta.to.shared.u64 t, %1; cvt.u32.u64 %0, t; }" : "=r"(a) : "l"(p));
    return a;
}
__device__ __forceinline__ u32 packhf(float a, float b) {
    __half2 h = __floats2half2_rn(a, b);
    return *(u32*)&h;
}
__device__ __forceinline__ float hlo(float x) {
    return x - __half2float(__float2half_rn(x));
}
// Accurate expTanh: exp(1 - 2/(e^{2x}+1))
__device__ __forceinline__ float expTanh(float x) {
    float e2 = __expf(2.0f * x);
    float th = 1.0f - __fdividef(2.0f, e2 + 1.0f);
    return __expf(th);
}
__device__ __forceinline__ void ldsm_x4(u32* r, u32 a) {
    asm volatile("ldmatrix.sync.aligned.m8n8.x4.shared.b16 {%0,%1,%2,%3}, [%4];"
                 : "=r"(r[0]), "=r"(r[1]), "=r"(r[2]), "=r"(r[3]) : "r"(a));
}
__device__ __forceinline__ void ldsm_x4t(u32* r, u32 a) {
    asm volatile("ldmatrix.sync.aligned.m8n8.x4.trans.shared.b16 {%0,%1,%2,%3}, [%4];"
                 : "=r"(r[0]), "=r"(r[1]), "=r"(r[2]), "=r"(r[3]) : "r"(a));
}
__device__ __forceinline__ void mma_hf(float* c, const u32* a, u32 b0, u32 b1) {
    asm volatile(
        "mma.sync.aligned.m16n8k16.row.col.f32.f16.f16.f32 "
        "{%0,%1,%2,%3}, {%4,%5,%6,%7}, {%8,%9}, {%0,%1,%2,%3};"
        : "+f"(c[0]), "+f"(c[1]), "+f"(c[2]), "+f"(c[3])
        : "r"(a[0]), "r"(a[1]), "r"(a[2]), "r"(a[3]), "r"(b0), "r"(b1));
}
__device__ __forceinline__ void cpa16(u32 smem, const void* g) {
    asm volatile("cp.async.cg.shared.global [%0], [%1], 16;" :: "r"(smem), "l"(g));
}
__device__ __forceinline__ void cpa_commit() { asm volatile("cp.async.commit_group;" ::: "memory"); }
template<int N> __device__ __forceinline__ void cpa_wait() {
    asm volatile("cp.async.wait_group %0;" :: "n"(N) : "memory");
}

// [64][128] f32 -> fp16 hi-only key tile
__device__ __forceinline__ void conv64_h(char* hi, const float* __restrict__ src, int tid) {
    const float4* s4 = (const float4*)src;
    #pragma unroll
    for (int it = 0; it < 4; ++it) {
        int li = tid + 256 * it;          // < 1024
        int r = li >> 4, c8 = li & 15;
        float4 v0 = s4[2 * li], v1 = s4[2 * li + 1];
        uint4 h = make_uint4(packhf(v0.x, v0.y), packhf(v0.z, v0.w),
                             packhf(v1.x, v1.y), packhf(v1.z, v1.w));
        *(uint4*)(hi + r * (SH * 2) + 16 * c8) = h;
    }
}
// [128][128] f32 -> fp16 hi-only tile (Xq)
__device__ __forceinline__ void conv128_h(char* hi, const float* __restrict__ src, int tid) {
    const float4* s4 = (const float4*)src;
    #pragma unroll
    for (int it = 0; it < 8; ++it) {
        int li = tid + 256 * it;          // < 2048
        int r = li >> 4, c8 = li & 15;
        float4 v0 = s4[2 * li], v1 = s4[2 * li + 1];
        uint4 h = make_uint4(packhf(v0.x, v0.y), packhf(v0.z, v0.w),
                             packhf(v1.x, v1.y), packhf(v1.z, v1.w));
        *(uint4*)(hi + r * (SH * 2) + 16 * c8) = h;
    }
}

// ---- prologue: W -> fp16 hi+lo pass images ----
__global__ void conv_w_kernel(const float* __restrict__ Wg) {
    int idx = blockIdx.x * blockDim.x + threadIdx.x;
    if (idx >= 4096) return;
    int p = idx >> 11, li = idx & 2047;
    int r = li >> 5, c4 = li & 31;
    const float4* s4 = (const float4*)(Wg + p * 64 * NE);
    float4 v = s4[li];
    uint2 h = make_uint2(packhf(v.x, v.y), packhf(v.z, v.w));
    uint2 l = make_uint2(packhf(hlo(v.x), hlo(v.y)), packhf(hlo(v.z), hlo(v.w)));
    int off = r * (SH * 2) + 8 * c4;
    *(uint2*)(g_Wbf[p] + off) = h;
    *(uint2*)(g_Wbf[p] + T64 + off) = l;
}

__global__ void __launch_bounds__(256, 2)
sent_attn_hmma7(const float* __restrict__ Xg, const float* __restrict__ Wg,
                const int* __restrict__ lens, float* __restrict__ out)
{
    extern __shared__ char sm[];
    const u32 sb = sm2u(sm);
    const int tid = threadIdx.x, lane = tid & 31, wid = tid >> 5;
    const int mg = wid >> 1;           // 0..3: 32-row query band
    const int ng = wid & 1;            // 0..1: col group (64 wide for G1/G3, 32 for G2)
    const int g = lane >> 2, tig = lane & 3;
    const int qc = blockIdx.x, bd = blockIdx.y;   // qc 0..1 (128-query chunks)
    const float* X = Xg + (size_t)bd * NS * NE;
    const int L = lens[bd];

    const int arow = (lane & 15);
    const int acol8 = (lane >> 4) << 3;

    // hoisted LDSM bases
    const u32 aA0 = sb + R_AH + (u32)(((32 * mg + arow) * SH + acol8) * 2);   // A / XW rows
    const u32 aW  = sb + R_KH + (u32)((arow * SH + 64 * ng + acol8) * 2);     // trans B (W / keys)
    const u32 aK2 = sb + R_KH + (u32)(((32 * ng + arow) * SH + acol8) * 2);   // G2 B (non-trans)
    const u32 aP0 = sb + R_PH + (u32)(((32 * mg + arow) * PSTR + acol8) * 2); // G3 A (P)

    // ---- W pass-0 hi+lo (34816B) via cp.async into KH+KL, overlapped with Xq conv ----
    for (int li = tid; li < 2176; li += 256)
        cpa16(sb + R_KH + li * 16, g_Wbf[0] + li * 16);
    cpa_commit();
    conv128_h(sm + R_AH, X + qc * 128 * NE, tid);
    cpa_wait<0>();
    __syncthreads();

    // ======= GEMM1: XW = Xq_hi @ (W_hi + W_lo), warp tile 32x64, trans B, two 64-k passes =======
    float c1[2][8][4];
    #pragma unroll
    for (int mt = 0; mt < 2; ++mt)
        #pragma unroll
        for (int nt = 0; nt < 8; ++nt)
            #pragma unroll
            for (int r = 0; r < 4; ++r) c1[mt][nt][r] = 0.f;

    #pragma unroll
    for (int p = 0; p < 2; ++p) {
        #pragma unroll
        for (int k0 = 0; k0 < 4; ++k0) {
            u32 ah[2][4];
            #pragma unroll
            for (int mt = 0; mt < 2; ++mt)
                ldsm_x4(ah[mt], aA0 + (u32)((16 * mt * SH + p * 64 + k0 * 16) * 2));
            u32 bh[16], bl[16];
            {
                u32 b0 = aW + (u32)(k0 * 16 * SH * 2);
                ldsm_x4t(bh, b0); ldsm_x4t(bh + 4, b0 + 32);
                ldsm_x4t(bh + 8, b0 + 64); ldsm_x4t(bh + 12, b0 + 96);
                u32 b1 = b0 + (u32)T64;
                ldsm_x4t(bl, b1); ldsm_x4t(bl + 4, b1 + 32);
                ldsm_x4t(bl + 8, b1 + 64); ldsm_x4t(bl + 12, b1 + 96);
            }
            #pragma unroll
            for (int mt = 0; mt < 2; ++mt)
                #pragma unroll
                for (int nt = 0; nt < 8; ++nt) {
                    mma_hf(c1[mt][nt], ah[mt], bh[2 * nt], bh[2 * nt + 1]);
                    mma_hf(c1[mt][nt], ah[mt], bl[2 * nt], bl[2 * nt + 1]);
                }
        }
        if (p == 0) {
            __syncthreads();                       // pass-0 W reads done
            for (int li = tid; li < 2176; li += 256)
                cpa16(sb + R_KH + li * 16, g_Wbf[1] + li * 16);
            cpa_commit();
            cpa_wait<0>();
            __syncthreads();
        }
    }
    __syncthreads();   // RACE FIX: sibling warps read A's full row-band in GEMM1

    // ---- epilogue 1: XW hi overwrites region A ----
    #pragma unroll
    for (int mt = 0; mt < 2; ++mt)
        #pragma unroll
        for (int nt = 0; nt < 8; ++nt)
            #pragma unroll
            for (int h = 0; h < 2; ++h) {
                int row = 32 * mg + 16 * mt + g + 8 * h;
                int col = 64 * ng + 8 * nt + 2 * tig;
                *(u32*)(sm + R_AH + (row * SH + col) * 2) = packhf(c1[mt][nt][2 * h], c1[mt][nt][2 * h + 1]);
            }

    // ---- persistent accumulators ----
    float c3[2][8][4];
    #pragma unroll
    for (int mt = 0; mt < 2; ++mt)
        #pragma unroll
        for (int nt = 0; nt < 8; ++nt)
            #pragma unroll
            for (int r = 0; r < 4; ++r) c3[mt][nt][r] = 0.f;
    float sumM[2][2];
    sumM[0][0] = sumM[0][1] = sumM[1][0] = sumM[1][1] = 0.f;

    const int nch = min(4, (L + 63) >> 6);   // 64-key chunks; keys >= L contribute 0
    for (int ct = 0; ct < nch; ++ct) {
        __syncthreads();                     // K region free (epi1 visible / prior G2,G3 reads done)
        conv64_h(sm + R_KH, X + ct * 64 * NE, tid);   // keys hi only
        __syncthreads();                     // K ready

        // ===== GEMM2: logits[128][64] = XWh @ keysh^T (1-term), warp tile 32x32 =====
        float c2[2][4][4];
        #pragma unroll
        for (int mt = 0; mt < 2; ++mt)
            #pragma unroll
            for (int nt = 0; nt < 4; ++nt)
                #pragma unroll
                for (int r = 0; r < 4; ++r) c2[mt][nt][r] = 0.f;

        #pragma unroll
        for (int k0 = 0; k0 < 8; ++k0) {
            u32 ah[2][4];
            #pragma unroll
            for (int mt = 0; mt < 2; ++mt)
                ldsm_x4(ah[mt], aA0 + (u32)((16 * mt * SH + k0 * 16) * 2));
            u32 kb[8];
            {
                u32 b0 = aK2 + (u32)(k0 * 32);
                ldsm_x4(kb, b0);
                ldsm_x4(kb + 4, b0 + (u32)(16 * SH * 2));
            }
            #pragma unroll
            for (int mt = 0; mt < 2; ++mt)
                #pragma unroll
                for (int nt = 0; nt < 4; ++nt) {
                    int q = nt >> 1, r2 = nt & 1;
                    mma_hf(c2[mt][nt], ah[mt], kb[4 * q + r2], kb[4 * q + r2 + 2]);
                }
        }

        // ---- epilogue 2: exp(tanh), mask, row sums, P hi ----
        #pragma unroll
        for (int mt = 0; mt < 2; ++mt)
            #pragma unroll
            for (int nt = 0; nt < 4; ++nt)
                #pragma unroll
                for (int h = 0; h < 2; ++h) {
                    int row = 32 * mg + 16 * mt + g + 8 * h;
                    int col = 32 * ng + 8 * nt + 2 * tig;
                    int t = ct * 64 + col;
                    float p0 = expTanh(c2[mt][nt][2 * h]);
                    float p1 = expTanh(c2[mt][nt][2 * h + 1]);
                    if (t     >= L) p0 = 0.f;
                    if (t + 1 >= L) p1 = 0.f;
                    sumM[mt][h] += p0 + p1;
                    *(u32*)(sm + R_PH + (row * PSTR + col) * 2) = packhf(p0, p1);
                }
        __syncthreads();   // P complete (cross-warp k reads in GEMM3)

        // ===== GEMM3: att += Ph @ keys-hi, warp tile 32x64, trans B, k=64 =====
        #pragma unroll
        for (int k0 = 0; k0 < 4; ++k0) {
            u32 ah[2][4];
            #pragma unroll
            for (int mt = 0; mt < 2; ++mt)
                ldsm_x4(ah[mt], aP0 + (u32)((16 * mt * PSTR + k0 * 16) * 2));
            u32 bw[16];
            {
                u32 b0 = aW + (u32)(k0 * 16 * SH * 2);
                ldsm_x4t(bw, b0); ldsm_x4t(bw + 4, b0 + 32);
                ldsm_x4t(bw + 8, b0 + 64); ldsm_x4t(bw + 12, b0 + 96);
            }
            #pragma unroll
            for (int mt = 0; mt < 2; ++mt)
                #pragma unroll
                for (int nt = 0; nt < 8; ++nt)
                    mma_hf(c3[mt][nt], ah[mt], bw[2 * nt], bw[2 * nt + 1]);
        }
    }

    // ---- row-sum reduction (2 ng halves per row) ----
    #pragma unroll
    for (int mt = 0; mt < 2; ++mt)
        #pragma unroll
        for (int h = 0; h < 2; ++h) {
            float v = sumM[mt][h];
            v += __shfl_xor_sync(0xffffffffu, v, 1);
            v += __shfl_xor_sync(0xffffffffu, v, 2);
            if (tig == 0) {
                int row = 32 * mg + 16 * mt + g + 8 * h;
                ((float*)(sm + R_RM))[row * 2 + ng] = v;
            }
        }
    __syncthreads();
    if (tid < 128) {
        const float* rm = (const float*)(sm + R_RM);
        ((float*)(sm + R_INV))[tid] = 1.0f / (rm[tid * 2] + rm[tid * 2 + 1]);
    }
    __syncthreads();

    // ---- output: renormalize, STG.64 ----
    float* obase = out + ((size_t)bd * NS + qc * 128) * NE;
    const float* invp = (const float*)(sm + R_INV);
    #pragma unroll
    for (int mt = 0; mt < 2; ++mt)
        #pragma unroll
        for (int h = 0; h < 2; ++h) {
            int row = 32 * mg + 16 * mt + g + 8 * h;
            float iv = invp[row];
            #pragma unroll
            for (int nt = 0; nt < 8; ++nt) {
                int col = 64 * ng + 8 * nt + 2 * tig;
                float2 v = make_float2(c3[mt][nt][2 * h] * iv, c3[mt][nt][2 * h + 1] * iv);
                *(float2*)(obase + row * NE + col) = v;
            }
        }
}

extern "C" void kernel_launch(void* const* d_in, const int* in_sizes, int n_in,
                              void* d_out, int out_size)
{
    const float* X    = (const float*)d_in[0];   // words_enc (8,64,256,128) f32
    const float* W    = (const float*)d_in[1];   // W (128,128) f32
    const int*   lens = (const int*)d_in[2];     // valid_words_len (8,64) i32
    float*       out  = (float*)d_out;           // (8,64,256,128) f32

    conv_w_kernel<<<16, 256>>>(W);               // preconvert W fp16 hi+lo pass images

    cudaFuncSetAttribute(sent_attn_hmma7, cudaFuncAttributeMaxDynamicSharedMemorySize, SMEM_BYTES);
    dim3 grid(2, NBD, 1);   // 2 query chunks x 512 sentences
    dim3 block(256, 1, 1);
    sent_attn_hmma7<<<grid, block, SMEM_BYTES>>>(X, W, lens, out);
}